// round 12
// baseline (speedup 1.0000x reference)
#include <cuda_runtime.h>
#include <cuda_bf16.h>
#include <cstdint>

// ---------------- problem constants ----------------------------------------
#define NB   2
#define LDIM 4800
#define SDIM 4800
#define CD   256
#define W0C  80
#define H0C  60
#define W1C  80
#define H1C  60
#define THRV 0.2f
#define SIM_SCALE 0.0390625f   // 1/(C*temp) = 1/(256*0.1)

#define NLT (NB*LDIM)
#define NST (NB*SDIM)
#define NCONF ((size_t)NB*(size_t)LDIM*(size_t)SDIM)

// GEMM tiling: 128(M) x 256(N) block tile, k-chunk 64, 8 warps (2M x 4N),
// warp tile 64x64, cp.async double-buffered.
#define ABUF_SZ 16384                    // 128 rows x 128 B
#define BBUF_SZ 32768                    // 256 rows x 128 B
#define OFF_AH 0
#define OFF_AL (ABUF_SZ)
#define OFF_BH (2*ABUF_SZ)
#define OFF_BL (2*ABUF_SZ + BBUF_SZ)
#define STAGE_SZ (2*ABUF_SZ + 2*BBUF_SZ) // 98304
#define SMEM_TOTAL (2*STAGE_SZ)          // 196608

// ---------------- device scratch -------------------------------------------
__device__ __align__(16) __nv_bfloat16 g_f0h[(size_t)NB*LDIM*CD];
__device__ __align__(16) __nv_bfloat16 g_f0l[(size_t)NB*LDIM*CD];
__device__ __align__(16) __nv_bfloat16 g_f1h[(size_t)NB*SDIM*CD];
__device__ __align__(16) __nv_bfloat16 g_f1l[(size_t)NB*SDIM*CD];
__device__ float g_e[(size_t)NB*LDIM*SDIM];     // exp(sim), 184 MB
__device__ float g_rsum[NLT];
__device__ float g_csum[NST];
__device__ unsigned long long g_rkey[NLT];      // (conf_bits<<32)|(SDIM-1-col)
__device__ unsigned g_ccmax[NST];

// ---------------- helpers ---------------------------------------------------
__device__ __forceinline__ unsigned smem_u32(const void* p) {
    unsigned a;
    asm("{ .reg .u64 t; cvta.to.shared.u64 t, %1; cvt.u32.u64 %0, t; }"
        : "=r"(a) : "l"(p));
    return a;
}
__device__ __forceinline__ unsigned swz(unsigned off) {
    return off ^ ((off >> 3) & 0x70);
}
#define LDSM4(r, a) \
    asm volatile("ldmatrix.sync.aligned.m8n8.x4.shared.b16 {%0,%1,%2,%3}, [%4];" \
        : "=r"((r)[0]), "=r"((r)[1]), "=r"((r)[2]), "=r"((r)[3]) : "r"(a))

#define CPA16(dst, src) \
    asm volatile("cp.async.cg.shared.global [%0], [%1], 16;" \
        :: "r"(dst), "l"(src) : "memory")
#define CPA_COMMIT() asm volatile("cp.async.commit_group;" ::: "memory")
#define CPA_WAIT1()  asm volatile("cp.async.wait_group 1;" ::: "memory")
#define CPA_WAIT0()  asm volatile("cp.async.wait_group 0;" ::: "memory")

__device__ __forceinline__ void mma16816(float* d, const unsigned* a,
                                         const unsigned* b) {
    asm volatile(
        "mma.sync.aligned.m16n8k16.row.col.f32.bf16.bf16.f32 "
        "{%0,%1,%2,%3}, {%4,%5,%6,%7}, {%8,%9}, {%0,%1,%2,%3};"
        : "+f"(d[0]), "+f"(d[1]), "+f"(d[2]), "+f"(d[3])
        : "r"(a[0]), "r"(a[1]), "r"(a[2]), "r"(a[3]), "r"(b[0]), "r"(b[1]));
}

// ---------------- kernel: init ---------------------------------------------
__global__ void k_init() {
    int i = blockIdx.x * 256 + threadIdx.x;
    if (i < NLT) { g_rsum[i] = 0.f; g_rkey[i] = 0ull; }
    if (i < NST) { g_csum[i] = 0.f; g_ccmax[i] = 0u; }
}

// ---------------- kernel: fp32 -> bf16 hi/lo split -------------------------
__device__ __forceinline__ unsigned pack_hi(float x, float y, float& lx, float& ly) {
    __nv_bfloat16 hx = __float2bfloat16_rn(x);
    __nv_bfloat16 hy = __float2bfloat16_rn(y);
    lx = x - __bfloat162float(hx);
    ly = y - __bfloat162float(hy);
    return ((unsigned)__bfloat16_as_ushort(hy) << 16) | (unsigned)__bfloat16_as_ushort(hx);
}
__device__ __forceinline__ unsigned pack_lo(float lx, float ly) {
    return ((unsigned)__bfloat16_as_ushort(__float2bfloat16_rn(ly)) << 16)
         | (unsigned)__bfloat16_as_ushort(__float2bfloat16_rn(lx));
}

__global__ void k_split(const float* __restrict__ f0, const float* __restrict__ f1) {
    int i = blockIdx.x * 256 + threadIdx.x;   // float4 group; 614400 total
    {
        float4 a = ((const float4*)f0)[i];
        a.x *= SIM_SCALE; a.y *= SIM_SCALE; a.z *= SIM_SCALE; a.w *= SIM_SCALE;
        float l0, l1, l2, l3;
        uint2 h, l;
        h.x = pack_hi(a.x, a.y, l0, l1);
        h.y = pack_hi(a.z, a.w, l2, l3);
        l.x = pack_lo(l0, l1);
        l.y = pack_lo(l2, l3);
        ((uint2*)g_f0h)[i] = h;
        ((uint2*)g_f0l)[i] = l;
    }
    {
        float4 a = ((const float4*)f1)[i];
        float l0, l1, l2, l3;
        uint2 h, l;
        h.x = pack_hi(a.x, a.y, l0, l1);
        h.y = pack_hi(a.z, a.w, l2, l3);
        l.x = pack_lo(l0, l1);
        l.y = pack_lo(l2, l3);
        ((uint2*)g_f1h)[i] = h;
        ((uint2*)g_f1l)[i] = l;
    }
}

// ---------------- kernel: HMMA split-bf16 GEMM + fused exp/sums ------------
// grid (19, 38, NB), 256 threads; 128x256 tile; cp.async double-buffered.
__global__ void __launch_bounds__(256, 1) k_gemm() {
    extern __shared__ char smem[];
    const unsigned sbase = smem_u32(smem);
    const int tid = threadIdx.x, wid = tid >> 5, lane = tid & 31;
    const int wm = wid & 1, wn = wid >> 1;      // 2M x 4N warps
    const int lm = lane >> 2, lq = lane & 3;
    const int n = blockIdx.z;
    const int l0 = blockIdx.y * 128;
    const int s0 = blockIdx.x * 256;

    // ---- per-thread cp.async geometry ----
    // A bufs: 1024 int4 each -> 4 per thread; B bufs: 2048 int4 -> 8 per thread
    const int4* srcAh[4]; const int4* srcAl[4];
    const int4* srcBh[8]; const int4* srcBl[8];
    unsigned dstA[4], dstB[8];
    {
        const int4* pAh = (const int4*)g_f0h + (size_t)n * LDIM * 32;
        const int4* pAl = (const int4*)g_f0l + (size_t)n * LDIM * 32;
        const int4* pBh = (const int4*)g_f1h + (size_t)n * SDIM * 32;
        const int4* pBl = (const int4*)g_f1l + (size_t)n * SDIM * 32;
#pragma unroll
        for (int i = 0; i < 4; i++) {
            int idx = tid + i * 256;
            int r = idx >> 3, j = idx & 7;
            int ra = min(l0 + r, LDIM - 1);
            srcAh[i] = pAh + (size_t)ra * 32 + j;
            srcAl[i] = pAl + (size_t)ra * 32 + j;
            dstA[i] = sbase + swz(r * 128 + j * 16);
        }
#pragma unroll
        for (int i = 0; i < 8; i++) {
            int idx = tid + i * 256;
            int r = idx >> 3, j = idx & 7;
            int rb = min(s0 + r, SDIM - 1);
            srcBh[i] = pBh + (size_t)rb * 32 + j;
            srcBl[i] = pBl + (size_t)rb * 32 + j;
            dstB[i] = sbase + swz(r * 128 + j * 16);
        }
    }

    // ---- ldmatrix addresses (stage 0; add STAGE_SZ for stage 1) ----
    unsigned aA[4], aB[4];
#pragma unroll
    for (int mf = 0; mf < 4; mf++) {
        unsigned row = wm * 64 + mf * 16 + (lane & 15);
        aA[mf] = sbase + (swz(row * 128) ^ ((lane >> 4) * 16));
    }
#pragma unroll
    for (int np = 0; np < 4; np++) {
        unsigned row = wn * 64 + np * 16 + ((lane >> 4) & 1) * 8 + (lane & 7);
        aB[np] = sbase + (swz(row * 128) ^ (((lane >> 3) & 1) * 16));
    }

    float acc[4][8][4];
#pragma unroll
    for (int mf = 0; mf < 4; mf++)
#pragma unroll
        for (int nf = 0; nf < 8; nf++)
#pragma unroll
            for (int q = 0; q < 4; q++) acc[mf][nf][q] = 0.f;

    // prologue: chunk 0 -> stage 0
#pragma unroll
    for (int i = 0; i < 4; i++) {
        CPA16(dstA[i] + OFF_AH, srcAh[i]);
        CPA16(dstA[i] + OFF_AL, srcAl[i]);
    }
#pragma unroll
    for (int i = 0; i < 8; i++) {
        CPA16(dstB[i] + OFF_BH, srcBh[i]);
        CPA16(dstB[i] + OFF_BL, srcBl[i]);
    }
    CPA_COMMIT();

    for (int c = 0; c < 4; c++) {
        if (c < 3) {
            const unsigned so = ((c + 1) & 1) * STAGE_SZ;
            const int ko = (c + 1) * 8;
#pragma unroll
            for (int i = 0; i < 4; i++) {
                CPA16(dstA[i] + so + OFF_AH, srcAh[i] + ko);
                CPA16(dstA[i] + so + OFF_AL, srcAl[i] + ko);
            }
#pragma unroll
            for (int i = 0; i < 8; i++) {
                CPA16(dstB[i] + so + OFF_BH, srcBh[i] + ko);
                CPA16(dstB[i] + so + OFF_BL, srcBl[i] + ko);
            }
            CPA_COMMIT();
            CPA_WAIT1();
        } else {
            CPA_WAIT0();
        }
        __syncthreads();

        const unsigned st = (c & 1) * STAGE_SZ;
#pragma unroll
        for (int ks = 0; ks < 4; ks++) {
            const unsigned kb = ks * 32;
            unsigned ah[4][4], al[4][4], bh[4][4], bl[4][4];
#pragma unroll
            for (int mf = 0; mf < 4; mf++) {
                LDSM4(ah[mf], ((aA[mf] ^ kb) + st) + OFF_AH);
                LDSM4(al[mf], ((aA[mf] ^ kb) + st) + OFF_AL);
            }
#pragma unroll
            for (int np = 0; np < 4; np++) {
                LDSM4(bh[np], ((aB[np] ^ kb) + st) + OFF_BH);
                LDSM4(bl[np], ((aB[np] ^ kb) + st) + OFF_BL);
            }
#pragma unroll
            for (int mf = 0; mf < 4; mf++)
#pragma unroll
                for (int np = 0; np < 4; np++) {
                    mma16816(acc[mf][2 * np + 0], ah[mf], &bh[np][0]);
                    mma16816(acc[mf][2 * np + 1], ah[mf], &bh[np][2]);
                }
#pragma unroll
            for (int mf = 0; mf < 4; mf++)
#pragma unroll
                for (int np = 0; np < 4; np++) {
                    mma16816(acc[mf][2 * np + 0], al[mf], &bh[np][0]);
                    mma16816(acc[mf][2 * np + 1], al[mf], &bh[np][2]);
                }
#pragma unroll
            for (int mf = 0; mf < 4; mf++)
#pragma unroll
                for (int np = 0; np < 4; np++) {
                    mma16816(acc[mf][2 * np + 0], ah[mf], &bl[np][0]);
                    mma16816(acc[mf][2 * np + 1], ah[mf], &bl[np][2]);
                }
        }
        __syncthreads();
    }

    // ---- epilogue: e = exp(sim), store, fused row/col sums ----
    float* srow = (float*)smem;          // [128]
    float* scol = srow + 128;            // [256]
    if (tid < 128) srow[tid] = 0.f;
    scol[tid] = 0.f;
    __syncthreads();

    float rs[4][2];
#pragma unroll
    for (int mf = 0; mf < 4; mf++) { rs[mf][0] = 0.f; rs[mf][1] = 0.f; }
    float cs[8][2];
#pragma unroll
    for (int nf = 0; nf < 8; nf++) { cs[nf][0] = 0.f; cs[nf][1] = 0.f; }

#pragma unroll
    for (int mf = 0; mf < 4; mf++) {
        const int row0 = l0 + wm * 64 + mf * 16 + lm;
        const int row1 = row0 + 8;
        const bool vr0 = row0 < LDIM, vr1 = row1 < LDIM;
        const size_t b0 = ((size_t)n * LDIM + row0) * SDIM;
        const size_t b1 = ((size_t)n * LDIM + row1) * SDIM;
#pragma unroll
        for (int nf = 0; nf < 8; nf++) {
            const int col = s0 + wn * 64 + nf * 8 + lq * 2;
            const bool vc = col < SDIM;
            float e0 = __expf(acc[mf][nf][0]);
            float e1 = __expf(acc[mf][nf][1]);
            float e2 = __expf(acc[mf][nf][2]);
            float e3 = __expf(acc[mf][nf][3]);
            if (vr0 & vc) __stcs((float2*)&g_e[b0 + col], make_float2(e0, e1));
            if (vr1 & vc) __stcs((float2*)&g_e[b1 + col], make_float2(e2, e3));
            if (vc) {
                rs[mf][0] += e0 + e1;
                rs[mf][1] += e2 + e3;
                float f0 = vr0 ? e0 : 0.f, f1 = vr0 ? e1 : 0.f;
                float f2 = vr1 ? e2 : 0.f, f3 = vr1 ? e3 : 0.f;
                cs[nf][0] += f0 + f2;
                cs[nf][1] += f1 + f3;
            }
        }
    }
    // row sums: reduce over the quad (lanes differing in bits 0-1)
#pragma unroll
    for (int mf = 0; mf < 4; mf++)
#pragma unroll
        for (int h = 0; h < 2; h++) {
            float v = rs[mf][h];
            v += __shfl_xor_sync(0xffffffffu, v, 1);
            v += __shfl_xor_sync(0xffffffffu, v, 2);
            if (lq == 0) atomicAdd(&srow[wm * 64 + mf * 16 + h * 8 + lm], v);
        }
    // col sums: reduce over lane bits 2-4
#pragma unroll
    for (int nf = 0; nf < 8; nf++)
#pragma unroll
        for (int p = 0; p < 2; p++) {
            float v = cs[nf][p];
            v += __shfl_xor_sync(0xffffffffu, v, 4);
            v += __shfl_xor_sync(0xffffffffu, v, 8);
            v += __shfl_xor_sync(0xffffffffu, v, 16);
            if (lm == 0) atomicAdd(&scol[wn * 64 + nf * 8 + lq * 2 + p], v);
        }
    __syncthreads();
    if (tid < 128) {
        if (l0 + tid < LDIM) atomicAdd(&g_rsum[n * LDIM + l0 + tid], srow[tid]);
    }
    if (s0 + tid < SDIM) atomicAdd(&g_csum[n * SDIM + s0 + tid], scol[tid]);
}

// ---------------- kernel: conf = e^2 * rinv * cinv + max tracking ----------
// grid (19, 75, NB), 256 threads: tile = 64 rows x 256 cols.
// Warp w owns rows r0+8w..r0+8w+7 (full 256-col span): private key max in the
// inner loop, one 5-shfl reduce per row, direct global atomicMax per row.
__global__ void __launch_bounds__(256) k_conf(float* __restrict__ out) {
    __shared__ unsigned swcol[8][256];
    const int n = blockIdx.z, r0 = blockIdx.y * 64, c0 = blockIdx.x * 256;
    const int tid = threadIdx.x, w = tid >> 5, lane = tid & 31;

    float rinv[8];
#pragma unroll
    for (int rr = 0; rr < 8; rr++)
        rinv[rr] = 1.0f / g_rsum[n * LDIM + r0 + w * 8 + rr];

    int cols[8]; bool cvv[8]; float cinv[8]; unsigned cmax[8];
#pragma unroll
    for (int i = 0; i < 8; i++) {
        cols[i] = c0 + i * 32 + lane;
        cvv[i] = cols[i] < SDIM;
        cinv[i] = cvv[i] ? 1.0f / g_csum[n * SDIM + cols[i]] : 0.f;
        cmax[i] = 0u;
    }

    const size_t base0 = ((size_t)n * LDIM + r0 + w * 8) * SDIM;
#pragma unroll
    for (int rr = 0; rr < 8; rr++) {
        const size_t rb = base0 + (size_t)rr * SDIM;
        unsigned long long key = 0ull;
#pragma unroll
        for (int i = 0; i < 8; i++) {
            float v = cvv[i] ? __ldcs(&g_e[rb + cols[i]]) : 0.f;
            float cf = v * v * rinv[rr] * cinv[i];
            if (cvv[i]) __stcs(&out[rb + cols[i]], cf);
            unsigned b = __float_as_uint(cf);
            cmax[i] = max(cmax[i], b);
            unsigned long long k2 =
                ((unsigned long long)b << 32) | (unsigned)(SDIM - 1 - cols[i]);
            key = (k2 > key) ? k2 : key;
        }
#pragma unroll
        for (int o = 16; o > 0; o >>= 1) {
            unsigned long long ok = __shfl_xor_sync(0xffffffffu, key, o);
            key = (ok > key) ? ok : key;
        }
        if (lane == 0) atomicMax(&g_rkey[n * LDIM + r0 + w * 8 + rr], key);
    }

#pragma unroll
    for (int i = 0; i < 8; i++) swcol[w][i * 32 + lane] = cmax[i];
    __syncthreads();
    unsigned m = 0u;
#pragma unroll
    for (int w2 = 0; w2 < 8; w2++) m = max(m, swcol[w2][tid]);
    if (c0 + tid < SDIM) atomicMax(&g_ccmax[n * SDIM + c0 + tid], m);
}

// ---------------- kernel: match extraction (O(L)) --------------------------
__global__ void k_extract(float* __restrict__ out) {
    int idx = blockIdx.x * 256 + threadIdx.x;
    if (idx >= NLT) return;
    const int n = idx / LDIM, r = idx - n * LDIM;

    float* pm = out + NCONF;
    float* pj = pm + NLT;
    float* pk = pj + NLT;
    float* pc = pk + 2 * NLT;

    unsigned long long key = g_rkey[idx];
    unsigned bits = (unsigned)(key >> 32);
    int c = SDIM - 1 - (int)(unsigned)(key & 0xffffffffu);
    float cf = __uint_as_float(bits);

    int i0 = r / W0C, j0 = r - i0 * W0C;
    int i1 = c / W1C, j1 = c - i1 * W1C;
    bool m = (cf > THRV)
          && (i0 >= 2) && (i0 < H0C - 2) && (j0 >= 2) && (j0 < W0C - 2)
          && (i1 >= 2) && (i1 < H1C - 2) && (j1 >= 2) && (j1 < W1C - 2)
          && (bits == g_ccmax[n * SDIM + c]);

    if (m) {
        pm[idx] = 1.f;
        pj[idx] = (float)c;
        pk[2 * idx]     = (float)j1;
        pk[2 * idx + 1] = (float)i1;
        pc[idx] = cf;
    } else {
        pm[idx] = 0.f;
        pj[idx] = 0.f;
        pk[2 * idx] = 0.f;
        pk[2 * idx + 1] = 0.f;
        pc[idx] = 0.f;
    }
}

// ---------------- launch ----------------------------------------------------
extern "C" void kernel_launch(void* const* d_in, const int* in_sizes, int n_in,
                              void* d_out, int out_size) {
    const float* f0 = (const float*)d_in[0];
    const float* f1 = (const float*)d_in[1];
    float* out = (float*)d_out;

    static int s_attr_done = 0;
    if (!s_attr_done) {
        cudaFuncSetAttribute(k_gemm, cudaFuncAttributeMaxDynamicSharedMemorySize,
                             SMEM_TOTAL);
        s_attr_done = 1;
    }

    k_init<<<38, 256>>>();
    k_split<<<2400, 256>>>(f0, f1);
    {
        dim3 g(19, 38, NB);
        k_gemm<<<g, 256, SMEM_TOTAL>>>();
    }
    {
        dim3 g(19, 75, NB);
        k_conf<<<g, 256>>>(out);
    }
    k_extract<<<38, 256>>>(out);
}

// round 13
// speedup vs baseline: 1.2543x; 1.2543x over previous
#include <cuda_runtime.h>
#include <cuda_bf16.h>
#include <cstdint>

// ---------------- problem constants ----------------------------------------
#define NB   2
#define LDIM 4800
#define SDIM 4800
#define CD   256
#define W0C  80
#define H0C  60
#define W1C  80
#define H1C  60
#define THRV 0.2f
#define SIM_SCALE 0.0390625f   // 1/(C*temp) = 1/(256*0.1)

#define NLT (NB*LDIM)
#define NST (NB*SDIM)
#define NCONF ((size_t)NB*(size_t)LDIM*(size_t)SDIM)

// GEMM tiling: 128x128 block tile, k-chunk 64 bf16, 8 warps (4 M x 2 N)
#define BUF_SZ 16384
#define STAGE_SZ (4*BUF_SZ)          // Ah, Al, Bh, Bl per stage
#define SMEM_TOTAL (2*STAGE_SZ)      // double buffered (128 KB)

// k_conf smem: 64 x 256 conf-bits tile + 64 rinv
#define CONF_SMEM (64*256*4 + 64*4)

// ---------------- device scratch -------------------------------------------
__device__ __align__(16) __nv_bfloat16 g_f0h[(size_t)NB*LDIM*CD];
__device__ __align__(16) __nv_bfloat16 g_f0l[(size_t)NB*LDIM*CD];
__device__ __align__(16) __nv_bfloat16 g_f1h[(size_t)NB*SDIM*CD];
__device__ __align__(16) __nv_bfloat16 g_f1l[(size_t)NB*SDIM*CD];
__device__ float g_e[(size_t)NB*LDIM*SDIM];     // exp(sim), 184 MB
__device__ float g_rsum[NLT];
__device__ float g_csum[NST];
__device__ unsigned long long g_rkey[NLT];      // (conf_bits<<32)|(SDIM-1-col)
__device__ unsigned g_ccmax[NST];

// ---------------- helpers ---------------------------------------------------
__device__ __forceinline__ unsigned smem_u32(const void* p) {
    unsigned a;
    asm("{ .reg .u64 t; cvta.to.shared.u64 t, %1; cvt.u32.u64 %0, t; }"
        : "=r"(a) : "l"(p));
    return a;
}
__device__ __forceinline__ unsigned swz(unsigned off) {
    return off ^ ((off >> 3) & 0x70);
}
#define LDSM4(r, a) \
    asm volatile("ldmatrix.sync.aligned.m8n8.x4.shared.b16 {%0,%1,%2,%3}, [%4];" \
        : "=r"((r)[0]), "=r"((r)[1]), "=r"((r)[2]), "=r"((r)[3]) : "r"(a))

#define CPA16(dst, src) \
    asm volatile("cp.async.cg.shared.global [%0], [%1], 16;" \
        :: "r"(dst), "l"(src) : "memory")
#define CPA_COMMIT() asm volatile("cp.async.commit_group;" ::: "memory")
#define CPA_WAIT1()  asm volatile("cp.async.wait_group 1;" ::: "memory")
#define CPA_WAIT0()  asm volatile("cp.async.wait_group 0;" ::: "memory")

__device__ __forceinline__ void mma16816(float* d, const unsigned* a,
                                         const unsigned* b) {
    asm volatile(
        "mma.sync.aligned.m16n8k16.row.col.f32.bf16.bf16.f32 "
        "{%0,%1,%2,%3}, {%4,%5,%6,%7}, {%8,%9}, {%0,%1,%2,%3};"
        : "+f"(d[0]), "+f"(d[1]), "+f"(d[2]), "+f"(d[3])
        : "r"(a[0]), "r"(a[1]), "r"(a[2]), "r"(a[3]), "r"(b[0]), "r"(b[1]));
}

// ---------------- kernel: init ---------------------------------------------
__global__ void k_init() {
    int i = blockIdx.x * 256 + threadIdx.x;
    if (i < NLT) { g_rsum[i] = 0.f; g_rkey[i] = 0ull; }
    if (i < NST) { g_csum[i] = 0.f; g_ccmax[i] = 0u; }
}

// ---------------- kernel: fp32 -> bf16 hi/lo split -------------------------
__device__ __forceinline__ unsigned pack_hi(float x, float y, float& lx, float& ly) {
    __nv_bfloat16 hx = __float2bfloat16_rn(x);
    __nv_bfloat16 hy = __float2bfloat16_rn(y);
    lx = x - __bfloat162float(hx);
    ly = y - __bfloat162float(hy);
    return ((unsigned)__bfloat16_as_ushort(hy) << 16) | (unsigned)__bfloat16_as_ushort(hx);
}
__device__ __forceinline__ unsigned pack_lo(float lx, float ly) {
    return ((unsigned)__bfloat16_as_ushort(__float2bfloat16_rn(ly)) << 16)
         | (unsigned)__bfloat16_as_ushort(__float2bfloat16_rn(lx));
}

__global__ void k_split(const float* __restrict__ f0, const float* __restrict__ f1) {
    int i = blockIdx.x * 256 + threadIdx.x;   // float4 group; 614400 total
    {
        float4 a = ((const float4*)f0)[i];
        a.x *= SIM_SCALE; a.y *= SIM_SCALE; a.z *= SIM_SCALE; a.w *= SIM_SCALE;
        float l0, l1, l2, l3;
        uint2 h, l;
        h.x = pack_hi(a.x, a.y, l0, l1);
        h.y = pack_hi(a.z, a.w, l2, l3);
        l.x = pack_lo(l0, l1);
        l.y = pack_lo(l2, l3);
        ((uint2*)g_f0h)[i] = h;
        ((uint2*)g_f0l)[i] = l;
    }
    {
        float4 a = ((const float4*)f1)[i];
        float l0, l1, l2, l3;
        uint2 h, l;
        h.x = pack_hi(a.x, a.y, l0, l1);
        h.y = pack_hi(a.z, a.w, l2, l3);
        l.x = pack_lo(l0, l1);
        l.y = pack_lo(l2, l3);
        ((uint2*)g_f1h)[i] = h;
        ((uint2*)g_f1l)[i] = l;
    }
}

// ---------------- kernel: HMMA split-bf16 GEMM + fused exp/sums ------------
// grid (38, 38, NB), 256 threads; cp.async double-buffered mainloop.
__global__ void __launch_bounds__(256, 1) k_gemm() {
    extern __shared__ char smem[];
    const unsigned sbase = smem_u32(smem);
    const int tid = threadIdx.x, wid = tid >> 5, lane = tid & 31;
    const int wm = wid & 3, wn = wid >> 2;
    const int lm = lane >> 2, lq = lane & 3;
    const int n = blockIdx.z;
    const int l0 = blockIdx.y * 128;
    const int s0 = blockIdx.x * 128;

    // ---- per-thread global load geometry (4 int4 per buffer) ----
    const int4* srcA[8];   // [0..3]=hi rows, [4..7]=lo rows
    const int4* srcB[8];
    unsigned dstu[4];
    {
        const int4* pAh = (const int4*)g_f0h + (size_t)n * LDIM * 32;
        const int4* pAl = (const int4*)g_f0l + (size_t)n * LDIM * 32;
        const int4* pBh = (const int4*)g_f1h + (size_t)n * SDIM * 32;
        const int4* pBl = (const int4*)g_f1l + (size_t)n * SDIM * 32;
#pragma unroll
        for (int i = 0; i < 4; i++) {
            int idx = tid + i * 256;
            int r = idx >> 3, j = idx & 7;
            int ra = min(l0 + r, LDIM - 1);
            int rb = min(s0 + r, SDIM - 1);
            srcA[i]     = pAh + (size_t)ra * 32 + j;
            srcA[4 + i] = pAl + (size_t)ra * 32 + j;
            srcB[i]     = pBh + (size_t)rb * 32 + j;
            srcB[4 + i] = pBl + (size_t)rb * 32 + j;
            dstu[i] = sbase + swz(r * 128 + j * 16);
        }
    }

    // ---- ldmatrix addresses (stage 0; add STAGE_SZ for stage 1) ----
    unsigned aA[2], aB[4];
#pragma unroll
    for (int mf = 0; mf < 2; mf++) {
        unsigned row = wm * 32 + mf * 16 + (lane & 15);
        aA[mf] = sbase + (swz(row * 128) ^ ((lane >> 4) * 16));
    }
#pragma unroll
    for (int np = 0; np < 4; np++) {
        unsigned row = wn * 64 + np * 16 + ((lane >> 4) & 1) * 8 + (lane & 7);
        aB[np] = sbase + (swz(row * 128) ^ (((lane >> 3) & 1) * 16));
    }

    float acc[2][8][4];
#pragma unroll
    for (int mf = 0; mf < 2; mf++)
#pragma unroll
        for (int nf = 0; nf < 8; nf++)
#pragma unroll
            for (int q = 0; q < 4; q++) acc[mf][nf][q] = 0.f;

    // prologue: issue chunk 0 into stage 0
#pragma unroll
    for (int i = 0; i < 4; i++) {
        CPA16(dstu[i],                      srcA[i]);
        CPA16(dstu[i] + BUF_SZ,             srcA[4 + i]);
        CPA16(dstu[i] + 2 * BUF_SZ,         srcB[i]);
        CPA16(dstu[i] + 3 * BUF_SZ,         srcB[4 + i]);
    }
    CPA_COMMIT();

    for (int c = 0; c < 4; c++) {
        if (c < 3) {
            const unsigned so = ((c + 1) & 1) * STAGE_SZ;
#pragma unroll
            for (int i = 0; i < 4; i++) {
                CPA16(dstu[i] + so,              srcA[i] + (c + 1) * 8);
                CPA16(dstu[i] + so + BUF_SZ,     srcA[4 + i] + (c + 1) * 8);
                CPA16(dstu[i] + so + 2 * BUF_SZ, srcB[i] + (c + 1) * 8);
                CPA16(dstu[i] + so + 3 * BUF_SZ, srcB[4 + i] + (c + 1) * 8);
            }
            CPA_COMMIT();
            CPA_WAIT1();
        } else {
            CPA_WAIT0();
        }
        __syncthreads();

        const unsigned st = (c & 1) * STAGE_SZ;
#pragma unroll
        for (int ks = 0; ks < 4; ks++) {
            const unsigned kb = ks * 32;
            unsigned ah[2][4], al[2][4], bh[4][4], bl[4][4];
#pragma unroll
            for (int mf = 0; mf < 2; mf++) {
                LDSM4(ah[mf], ((aA[mf] ^ kb) + st));
                LDSM4(al[mf], ((aA[mf] ^ kb) + st) + BUF_SZ);
            }
#pragma unroll
            for (int np = 0; np < 4; np++) {
                LDSM4(bh[np], ((aB[np] ^ kb) + st) + 2 * BUF_SZ);
                LDSM4(bl[np], ((aB[np] ^ kb) + st) + 3 * BUF_SZ);
            }
#pragma unroll
            for (int mf = 0; mf < 2; mf++)
#pragma unroll
                for (int np = 0; np < 4; np++) {
                    mma16816(acc[mf][2 * np + 0], ah[mf], &bh[np][0]);
                    mma16816(acc[mf][2 * np + 1], ah[mf], &bh[np][2]);
                }
#pragma unroll
            for (int mf = 0; mf < 2; mf++)
#pragma unroll
                for (int np = 0; np < 4; np++) {
                    mma16816(acc[mf][2 * np + 0], al[mf], &bh[np][0]);
                    mma16816(acc[mf][2 * np + 1], al[mf], &bh[np][2]);
                }
#pragma unroll
            for (int mf = 0; mf < 2; mf++)
#pragma unroll
                for (int np = 0; np < 4; np++) {
                    mma16816(acc[mf][2 * np + 0], ah[mf], &bl[np][0]);
                    mma16816(acc[mf][2 * np + 1], ah[mf], &bl[np][2]);
                }
        }
        __syncthreads();
    }

    // ---- epilogue: e = exp(sim), store, fused row/col sums ----
    float* srow = (float*)smem;          // [128]
    float* scol = srow + 128;            // [128]
    if (tid < 128) { srow[tid] = 0.f; scol[tid] = 0.f; }
    __syncthreads();

    float rs[2][2] = {{0.f, 0.f}, {0.f, 0.f}};
    float cs[8][2];
#pragma unroll
    for (int nf = 0; nf < 8; nf++) { cs[nf][0] = 0.f; cs[nf][1] = 0.f; }

#pragma unroll
    for (int mf = 0; mf < 2; mf++) {
        const int row0 = l0 + wm * 32 + mf * 16 + lm;
        const int row1 = row0 + 8;
        const bool vr0 = row0 < LDIM, vr1 = row1 < LDIM;
        const size_t b0 = ((size_t)n * LDIM + row0) * SDIM;
        const size_t b1 = ((size_t)n * LDIM + row1) * SDIM;
#pragma unroll
        for (int nf = 0; nf < 8; nf++) {
            const int col = s0 + wn * 64 + nf * 8 + lq * 2;
            const bool vc = col < SDIM;
            float e0 = __expf(acc[mf][nf][0]);
            float e1 = __expf(acc[mf][nf][1]);
            float e2 = __expf(acc[mf][nf][2]);
            float e3 = __expf(acc[mf][nf][3]);
            if (vr0 & vc) __stcs((float2*)&g_e[b0 + col], make_float2(e0, e1));
            if (vr1 & vc) __stcs((float2*)&g_e[b1 + col], make_float2(e2, e3));
            if (vc) {
                rs[mf][0] += e0 + e1;
                rs[mf][1] += e2 + e3;
                float f0 = vr0 ? e0 : 0.f, f1 = vr0 ? e1 : 0.f;
                float f2 = vr1 ? e2 : 0.f, f3 = vr1 ? e3 : 0.f;
                cs[nf][0] += f0 + f2;
                cs[nf][1] += f1 + f3;
            }
        }
    }
    // row sums: reduce over the quad (lanes differing in bits 0-1)
#pragma unroll
    for (int mf = 0; mf < 2; mf++)
#pragma unroll
        for (int h = 0; h < 2; h++) {
            float v = rs[mf][h];
            v += __shfl_xor_sync(0xffffffffu, v, 1);
            v += __shfl_xor_sync(0xffffffffu, v, 2);
            if (lq == 0) atomicAdd(&srow[wm * 32 + mf * 16 + h * 8 + lm], v);
        }
    // col sums: reduce over lane bits 2-4
#pragma unroll
    for (int nf = 0; nf < 8; nf++)
#pragma unroll
        for (int p = 0; p < 2; p++) {
            float v = cs[nf][p];
            v += __shfl_xor_sync(0xffffffffu, v, 4);
            v += __shfl_xor_sync(0xffffffffu, v, 8);
            v += __shfl_xor_sync(0xffffffffu, v, 16);
            if (lm == 0) atomicAdd(&scol[wn * 64 + nf * 8 + lq * 2 + p], v);
        }
    __syncthreads();
    if (tid < 128) {
        if (l0 + tid < LDIM) atomicAdd(&g_rsum[n * LDIM + l0 + tid], srow[tid]);
        if (s0 + tid < SDIM) atomicAdd(&g_csum[n * SDIM + s0 + tid], scol[tid]);
    }
}

// ---------------- kernel: conf = e^2 * rinv * cinv, two-phase --------------
// grid (19, 75, NB), 256 threads: tile = 64 rows x 256 cols.
// Phase 1: pure streaming (no warp collectives): conf -> out + smem tile,
//          private col-max register.
// Phase 2: warp w reduces rows 8w..8w+7 from smem (lane-private 8-col chunk,
//          one shfl-reduce per row), atomicMax per row.
__global__ void __launch_bounds__(256) k_conf(float* __restrict__ out) {
    extern __shared__ unsigned csm[];            // [64][256] conf bits
    float* srinv = (float*)(csm + 64 * 256);     // [64]
    const int n = blockIdx.z, r0 = blockIdx.y * 64, c0 = blockIdx.x * 256;
    const int tid = threadIdx.x, w = tid >> 5, lane = tid & 31;
    const int col = c0 + tid;
    const bool cv = col < SDIM;

    if (tid < 64) srinv[tid] = 1.0f / g_rsum[n * LDIM + r0 + tid];
    __syncthreads();
    const float cinv = cv ? 1.0f / g_csum[n * SDIM + col] : 0.f;
    unsigned cmax = 0u;
    const size_t ebase = ((size_t)n * LDIM + r0) * SDIM + col;

#pragma unroll 8
    for (int rr = 0; rr < 64; rr++) {
        const size_t off = ebase + (size_t)rr * SDIM;
        float v = cv ? __ldcs(&g_e[off]) : 0.f;
        float cf = v * v * srinv[rr] * cinv;
        if (cv) __stcs(&out[off], cf);
        unsigned b = __float_as_uint(cf);
        csm[rr * 256 + tid] = b;
        cmax = max(cmax, b);
    }
    if (cv) atomicMax(&g_ccmax[n * SDIM + col], cmax);
    __syncthreads();

    // phase 2: row argmax from smem
#pragma unroll
    for (int rr = 0; rr < 8; rr++) {
        const int row = w * 8 + rr;
        const unsigned* p = &csm[row * 256 + lane * 8];
        unsigned long long key = 0ull;
#pragma unroll
        for (int i = 0; i < 8; i++) {
            int lcol = c0 + lane * 8 + i;
            unsigned long long k2 =
                ((unsigned long long)p[i] << 32) | (unsigned)(SDIM - 1 - lcol);
            key = (k2 > key) ? k2 : key;
        }
#pragma unroll
        for (int o = 16; o > 0; o >>= 1) {
            unsigned long long ok = __shfl_xor_sync(0xffffffffu, key, o);
            key = (ok > key) ? ok : key;
        }
        if (lane == 0) atomicMax(&g_rkey[n * LDIM + r0 + row], key);
    }
}

// ---------------- kernel: match extraction (O(L)) --------------------------
__global__ void k_extract(float* __restrict__ out) {
    int idx = blockIdx.x * 256 + threadIdx.x;
    if (idx >= NLT) return;
    const int n = idx / LDIM, r = idx - n * LDIM;

    float* pm = out + NCONF;
    float* pj = pm + NLT;
    float* pk = pj + NLT;
    float* pc = pk + 2 * NLT;

    unsigned long long key = g_rkey[idx];
    unsigned bits = (unsigned)(key >> 32);
    int c = SDIM - 1 - (int)(unsigned)(key & 0xffffffffu);
    float cf = __uint_as_float(bits);

    int i0 = r / W0C, j0 = r - i0 * W0C;
    int i1 = c / W1C, j1 = c - i1 * W1C;
    bool m = (cf > THRV)
          && (i0 >= 2) && (i0 < H0C - 2) && (j0 >= 2) && (j0 < W0C - 2)
          && (i1 >= 2) && (i1 < H1C - 2) && (j1 >= 2) && (j1 < W1C - 2)
          && (bits == g_ccmax[n * SDIM + c]);

    if (m) {
        pm[idx] = 1.f;
        pj[idx] = (float)c;
        pk[2 * idx]     = (float)j1;
        pk[2 * idx + 1] = (float)i1;
        pc[idx] = cf;
    } else {
        pm[idx] = 0.f;
        pj[idx] = 0.f;
        pk[2 * idx] = 0.f;
        pk[2 * idx + 1] = 0.f;
        pc[idx] = 0.f;
    }
}

// ---------------- launch ----------------------------------------------------
extern "C" void kernel_launch(void* const* d_in, const int* in_sizes, int n_in,
                              void* d_out, int out_size) {
    const float* f0 = (const float*)d_in[0];
    const float* f1 = (const float*)d_in[1];
    float* out = (float*)d_out;

    static int s_attr_done = 0;
    if (!s_attr_done) {
        cudaFuncSetAttribute(k_gemm, cudaFuncAttributeMaxDynamicSharedMemorySize,
                             SMEM_TOTAL);
        cudaFuncSetAttribute(k_conf, cudaFuncAttributeMaxDynamicSharedMemorySize,
                             CONF_SMEM);
        s_attr_done = 1;
    }

    k_init<<<38, 256>>>();
    k_split<<<2400, 256>>>(f0, f1);
    {
        dim3 g(38, 38, NB);
        k_gemm<<<g, 256, SMEM_TOTAL>>>();
    }
    {
        dim3 g(19, 75, NB);
        k_conf<<<g, 256, CONF_SMEM>>>(out);
    }
    k_extract<<<38, 256>>>(out);
}

// round 14
// speedup vs baseline: 1.5655x; 1.2482x over previous
#include <cuda_runtime.h>
#include <cuda_bf16.h>
#include <cstdint>

// ---------------- problem constants ----------------------------------------
#define NB   2
#define LDIM 4800
#define SDIM 4800
#define CD   256
#define W0C  80
#define H0C  60
#define W1C  80
#define H1C  60
#define THRV 0.2f
#define SIM_SCALE 0.0390625f   // 1/(C*temp) = 1/(256*0.1)

#define NLT (NB*LDIM)
#define NST (NB*SDIM)
#define NCONF ((size_t)NB*(size_t)LDIM*(size_t)SDIM)

// GEMM tiling: 128x128 block tile, k-chunk 64 bf16, 8 warps (4 M x 2 N)
#define BUF_SZ 16384
#define STAGE_SZ (4*BUF_SZ)          // Ah, Al, Bh, Bl per stage (64 KB)
#define SMEM_TOTAL (3*STAGE_SZ)      // 3-stage pipeline (192 KB)

// k_conf smem: 32 x 256 conf-bits tile + 32 rinv
#define CONF_SMEM (32*256*4 + 32*4)

// ---------------- device scratch -------------------------------------------
__device__ __align__(16) __nv_bfloat16 g_f0h[(size_t)NB*LDIM*CD];
__device__ __align__(16) __nv_bfloat16 g_f0l[(size_t)NB*LDIM*CD];
__device__ __align__(16) __nv_bfloat16 g_f1h[(size_t)NB*SDIM*CD];
__device__ __align__(16) __nv_bfloat16 g_f1l[(size_t)NB*SDIM*CD];
__device__ float g_e[(size_t)NB*LDIM*SDIM];     // exp(sim), 184 MB
__device__ float g_rsum[NLT];
__device__ float g_csum[NST];
__device__ unsigned long long g_rkey[NLT];      // (conf_bits<<32)|(SDIM-1-col)
__device__ unsigned g_ccmax[NST];

// ---------------- helpers ---------------------------------------------------
__device__ __forceinline__ unsigned smem_u32(const void* p) {
    unsigned a;
    asm("{ .reg .u64 t; cvta.to.shared.u64 t, %1; cvt.u32.u64 %0, t; }"
        : "=r"(a) : "l"(p));
    return a;
}
__device__ __forceinline__ unsigned swz(unsigned off) {
    return off ^ ((off >> 3) & 0x70);
}
#define LDSM4(r, a) \
    asm volatile("ldmatrix.sync.aligned.m8n8.x4.shared.b16 {%0,%1,%2,%3}, [%4];" \
        : "=r"((r)[0]), "=r"((r)[1]), "=r"((r)[2]), "=r"((r)[3]) : "r"(a))

#define CPA16(dst, src) \
    asm volatile("cp.async.cg.shared.global [%0], [%1], 16;" \
        :: "r"(dst), "l"(src) : "memory")
#define CPA_COMMIT() asm volatile("cp.async.commit_group;" ::: "memory")
#define CPA_WAIT2()  asm volatile("cp.async.wait_group 2;" ::: "memory")
#define CPA_WAIT1()  asm volatile("cp.async.wait_group 1;" ::: "memory")
#define CPA_WAIT0()  asm volatile("cp.async.wait_group 0;" ::: "memory")

__device__ __forceinline__ void mma16816(float* d, const unsigned* a,
                                         const unsigned* b) {
    asm volatile(
        "mma.sync.aligned.m16n8k16.row.col.f32.bf16.bf16.f32 "
        "{%0,%1,%2,%3}, {%4,%5,%6,%7}, {%8,%9}, {%0,%1,%2,%3};"
        : "+f"(d[0]), "+f"(d[1]), "+f"(d[2]), "+f"(d[3])
        : "r"(a[0]), "r"(a[1]), "r"(a[2]), "r"(a[3]), "r"(b[0]), "r"(b[1]));
}

// ---------------- kernel: init ---------------------------------------------
__global__ void k_init() {
    int i = blockIdx.x * 256 + threadIdx.x;
    if (i < NLT) { g_rsum[i] = 0.f; g_rkey[i] = 0ull; }
    if (i < NST) { g_csum[i] = 0.f; g_ccmax[i] = 0u; }
}

// ---------------- kernel: fp32 -> bf16 hi/lo split -------------------------
__device__ __forceinline__ unsigned pack_hi(float x, float y, float& lx, float& ly) {
    __nv_bfloat16 hx = __float2bfloat16_rn(x);
    __nv_bfloat16 hy = __float2bfloat16_rn(y);
    lx = x - __bfloat162float(hx);
    ly = y - __bfloat162float(hy);
    return ((unsigned)__bfloat16_as_ushort(hy) << 16) | (unsigned)__bfloat16_as_ushort(hx);
}
__device__ __forceinline__ unsigned pack_lo(float lx, float ly) {
    return ((unsigned)__bfloat16_as_ushort(__float2bfloat16_rn(ly)) << 16)
         | (unsigned)__bfloat16_as_ushort(__float2bfloat16_rn(lx));
}

__global__ void k_split(const float* __restrict__ f0, const float* __restrict__ f1) {
    int i = blockIdx.x * 256 + threadIdx.x;   // float4 group; 614400 total
    {
        float4 a = ((const float4*)f0)[i];
        a.x *= SIM_SCALE; a.y *= SIM_SCALE; a.z *= SIM_SCALE; a.w *= SIM_SCALE;
        float l0, l1, l2, l3;
        uint2 h, l;
        h.x = pack_hi(a.x, a.y, l0, l1);
        h.y = pack_hi(a.z, a.w, l2, l3);
        l.x = pack_lo(l0, l1);
        l.y = pack_lo(l2, l3);
        ((uint2*)g_f0h)[i] = h;
        ((uint2*)g_f0l)[i] = l;
    }
    {
        float4 a = ((const float4*)f1)[i];
        float l0, l1, l2, l3;
        uint2 h, l;
        h.x = pack_hi(a.x, a.y, l0, l1);
        h.y = pack_hi(a.z, a.w, l2, l3);
        l.x = pack_lo(l0, l1);
        l.y = pack_lo(l2, l3);
        ((uint2*)g_f1h)[i] = h;
        ((uint2*)g_f1l)[i] = l;
    }
}

// ---------------- kernel: HMMA split-bf16 GEMM + fused exp/sums ------------
// grid (38, 38, NB), 256 threads; cp.async 3-stage pipelined mainloop.
__global__ void __launch_bounds__(256, 1) k_gemm() {
    extern __shared__ char smem[];
    const unsigned sbase = smem_u32(smem);
    const int tid = threadIdx.x, wid = tid >> 5, lane = tid & 31;
    const int wm = wid & 3, wn = wid >> 2;
    const int lm = lane >> 2, lq = lane & 3;
    const int n = blockIdx.z;
    const int l0 = blockIdx.y * 128;
    const int s0 = blockIdx.x * 128;

    // ---- per-thread global load geometry (4 int4 per buffer) ----
    const int4* srcA[8];   // [0..3]=hi rows, [4..7]=lo rows
    const int4* srcB[8];
    unsigned dstu[4];
    {
        const int4* pAh = (const int4*)g_f0h + (size_t)n * LDIM * 32;
        const int4* pAl = (const int4*)g_f0l + (size_t)n * LDIM * 32;
        const int4* pBh = (const int4*)g_f1h + (size_t)n * SDIM * 32;
        const int4* pBl = (const int4*)g_f1l + (size_t)n * SDIM * 32;
#pragma unroll
        for (int i = 0; i < 4; i++) {
            int idx = tid + i * 256;
            int r = idx >> 3, j = idx & 7;
            int ra = min(l0 + r, LDIM - 1);
            int rb = min(s0 + r, SDIM - 1);
            srcA[i]     = pAh + (size_t)ra * 32 + j;
            srcA[4 + i] = pAl + (size_t)ra * 32 + j;
            srcB[i]     = pBh + (size_t)rb * 32 + j;
            srcB[4 + i] = pBl + (size_t)rb * 32 + j;
            dstu[i] = sbase + swz(r * 128 + j * 16);
        }
    }

    // ---- ldmatrix addresses (stage 0; add s*STAGE_SZ for stage s) ----
    unsigned aA[2], aB[4];
#pragma unroll
    for (int mf = 0; mf < 2; mf++) {
        unsigned row = wm * 32 + mf * 16 + (lane & 15);
        aA[mf] = sbase + (swz(row * 128) ^ ((lane >> 4) * 16));
    }
#pragma unroll
    for (int np = 0; np < 4; np++) {
        unsigned row = wn * 64 + np * 16 + ((lane >> 4) & 1) * 8 + (lane & 7);
        aB[np] = sbase + (swz(row * 128) ^ (((lane >> 3) & 1) * 16));
    }

    float acc[2][8][4];
#pragma unroll
    for (int mf = 0; mf < 2; mf++)
#pragma unroll
        for (int nf = 0; nf < 8; nf++)
#pragma unroll
            for (int q = 0; q < 4; q++) acc[mf][nf][q] = 0.f;

    // issue chunk `ck` into stage offset `so`
#define ISSUE_CHUNK(ck, so) do {                                             \
    const int _ko = (ck) * 8;                                                \
    _Pragma("unroll")                                                        \
    for (int i = 0; i < 4; i++) {                                            \
        CPA16(dstu[i] + (so),              srcA[i] + _ko);                   \
        CPA16(dstu[i] + (so) + BUF_SZ,     srcA[4 + i] + _ko);               \
        CPA16(dstu[i] + (so) + 2 * BUF_SZ, srcB[i] + _ko);                   \
        CPA16(dstu[i] + (so) + 3 * BUF_SZ, srcB[4 + i] + _ko);               \
    }                                                                        \
    CPA_COMMIT();                                                            \
} while (0)

    // prologue: chunks 0,1 into stages 0,1
    ISSUE_CHUNK(0, 0);
    ISSUE_CHUNK(1, STAGE_SZ);

    for (int c = 0; c < 4; c++) {
        if (c < 2) {
            const unsigned so = ((c + 2) % 3) * STAGE_SZ;
            ISSUE_CHUNK(c + 2, so);
            CPA_WAIT2();
        } else if (c == 2) {
            CPA_WAIT1();
        } else {
            CPA_WAIT0();
        }
        __syncthreads();

        const unsigned st = (c % 3) * STAGE_SZ;
#pragma unroll
        for (int ks = 0; ks < 4; ks++) {
            const unsigned kb = ks * 32;
            unsigned ah[2][4], al[2][4], bh[4][4], bl[4][4];
#pragma unroll
            for (int mf = 0; mf < 2; mf++) {
                LDSM4(ah[mf], ((aA[mf] ^ kb) + st));
                LDSM4(al[mf], ((aA[mf] ^ kb) + st) + BUF_SZ);
            }
#pragma unroll
            for (int np = 0; np < 4; np++) {
                LDSM4(bh[np], ((aB[np] ^ kb) + st) + 2 * BUF_SZ);
                LDSM4(bl[np], ((aB[np] ^ kb) + st) + 3 * BUF_SZ);
            }
#pragma unroll
            for (int mf = 0; mf < 2; mf++)
#pragma unroll
                for (int np = 0; np < 4; np++) {
                    mma16816(acc[mf][2 * np + 0], ah[mf], &bh[np][0]);
                    mma16816(acc[mf][2 * np + 1], ah[mf], &bh[np][2]);
                }
#pragma unroll
            for (int mf = 0; mf < 2; mf++)
#pragma unroll
                for (int np = 0; np < 4; np++) {
                    mma16816(acc[mf][2 * np + 0], al[mf], &bh[np][0]);
                    mma16816(acc[mf][2 * np + 1], al[mf], &bh[np][2]);
                }
#pragma unroll
            for (int mf = 0; mf < 2; mf++)
#pragma unroll
                for (int np = 0; np < 4; np++) {
                    mma16816(acc[mf][2 * np + 0], ah[mf], &bl[np][0]);
                    mma16816(acc[mf][2 * np + 1], ah[mf], &bl[np][2]);
                }
        }
        __syncthreads();
    }

    // ---- epilogue: e = exp(sim), store, fused row/col sums ----
    float* srow = (float*)smem;          // [128]
    float* scol = srow + 128;            // [128]
    if (tid < 128) { srow[tid] = 0.f; scol[tid] = 0.f; }
    __syncthreads();

    float rs[2][2] = {{0.f, 0.f}, {0.f, 0.f}};
    float cs[8][2];
#pragma unroll
    for (int nf = 0; nf < 8; nf++) { cs[nf][0] = 0.f; cs[nf][1] = 0.f; }

#pragma unroll
    for (int mf = 0; mf < 2; mf++) {
        const int row0 = l0 + wm * 32 + mf * 16 + lm;
        const int row1 = row0 + 8;
        const bool vr0 = row0 < LDIM, vr1 = row1 < LDIM;
        const size_t b0 = ((size_t)n * LDIM + row0) * SDIM;
        const size_t b1 = ((size_t)n * LDIM + row1) * SDIM;
#pragma unroll
        for (int nf = 0; nf < 8; nf++) {
            const int col = s0 + wn * 64 + nf * 8 + lq * 2;
            const bool vc = col < SDIM;
            float e0 = __expf(acc[mf][nf][0]);
            float e1 = __expf(acc[mf][nf][1]);
            float e2 = __expf(acc[mf][nf][2]);
            float e3 = __expf(acc[mf][nf][3]);
            if (vr0 & vc) __stcs((float2*)&g_e[b0 + col], make_float2(e0, e1));
            if (vr1 & vc) __stcs((float2*)&g_e[b1 + col], make_float2(e2, e3));
            if (vc) {
                rs[mf][0] += e0 + e1;
                rs[mf][1] += e2 + e3;
                float f0 = vr0 ? e0 : 0.f, f1 = vr0 ? e1 : 0.f;
                float f2 = vr1 ? e2 : 0.f, f3 = vr1 ? e3 : 0.f;
                cs[nf][0] += f0 + f2;
                cs[nf][1] += f1 + f3;
            }
        }
    }
    // row sums: reduce over the quad (lanes differing in bits 0-1)
#pragma unroll
    for (int mf = 0; mf < 2; mf++)
#pragma unroll
        for (int h = 0; h < 2; h++) {
            float v = rs[mf][h];
            v += __shfl_xor_sync(0xffffffffu, v, 1);
            v += __shfl_xor_sync(0xffffffffu, v, 2);
            if (lq == 0) atomicAdd(&srow[wm * 32 + mf * 16 + h * 8 + lm], v);
        }
    // col sums: reduce over lane bits 2-4
#pragma unroll
    for (int nf = 0; nf < 8; nf++)
#pragma unroll
        for (int p = 0; p < 2; p++) {
            float v = cs[nf][p];
            v += __shfl_xor_sync(0xffffffffu, v, 4);
            v += __shfl_xor_sync(0xffffffffu, v, 8);
            v += __shfl_xor_sync(0xffffffffu, v, 16);
            if (lm == 0) atomicAdd(&scol[wn * 64 + nf * 8 + lq * 2 + p], v);
        }
    __syncthreads();
    if (tid < 128) {
        if (l0 + tid < LDIM) atomicAdd(&g_rsum[n * LDIM + l0 + tid], srow[tid]);
        if (s0 + tid < SDIM) atomicAdd(&g_csum[n * SDIM + s0 + tid], scol[tid]);
    }
}

// ---------------- kernel: conf = e^2 * rinv * cinv, two-phase --------------
// grid (19, 150, NB), 256 threads: tile = 32 rows x 256 cols (32 KB smem ->
// ~7 CTAs/SM). Phase 1: pure streaming, no warp collectives. Phase 2: row
// argmax from smem (4 rows per warp, one shfl-reduce per row).
__global__ void __launch_bounds__(256) k_conf(float* __restrict__ out) {
    extern __shared__ unsigned csm[];            // [32][256] conf bits
    float* srinv = (float*)(csm + 32 * 256);     // [32]
    const int n = blockIdx.z, r0 = blockIdx.y * 32, c0 = blockIdx.x * 256;
    const int tid = threadIdx.x, w = tid >> 5, lane = tid & 31;
    const int col = c0 + tid;
    const bool cv = col < SDIM;

    if (tid < 32) srinv[tid] = 1.0f / g_rsum[n * LDIM + r0 + tid];
    __syncthreads();
    const float cinv = cv ? 1.0f / g_csum[n * SDIM + col] : 0.f;
    unsigned cmax = 0u;
    const size_t ebase = ((size_t)n * LDIM + r0) * SDIM + col;

#pragma unroll 8
    for (int rr = 0; rr < 32; rr++) {
        const size_t off = ebase + (size_t)rr * SDIM;
        float v = cv ? __ldcs(&g_e[off]) : 0.f;
        float cf = v * v * srinv[rr] * cinv;
        if (cv) __stcs(&out[off], cf);
        unsigned b = __float_as_uint(cf);
        csm[rr * 256 + tid] = b;
        cmax = max(cmax, b);
    }
    if (cv) atomicMax(&g_ccmax[n * SDIM + col], cmax);
    __syncthreads();

    // phase 2: row argmax from smem; warp w -> rows 4w..4w+3
#pragma unroll
    for (int rr = 0; rr < 4; rr++) {
        const int row = w * 4 + rr;
        const unsigned* p = &csm[row * 256 + lane * 8];
        unsigned long long key = 0ull;
#pragma unroll
        for (int i = 0; i < 8; i++) {
            int lcol = c0 + lane * 8 + i;
            unsigned long long k2 =
                ((unsigned long long)p[i] << 32) | (unsigned)(SDIM - 1 - lcol);
            key = (k2 > key) ? k2 : key;
        }
#pragma unroll
        for (int o = 16; o > 0; o >>= 1) {
            unsigned long long ok = __shfl_xor_sync(0xffffffffu, key, o);
            key = (ok > key) ? ok : key;
        }
        if (lane == 0) atomicMax(&g_rkey[n * LDIM + r0 + row], key);
    }
}

// ---------------- kernel: match extraction (O(L)) --------------------------
__global__ void k_extract(float* __restrict__ out) {
    int idx = blockIdx.x * 256 + threadIdx.x;
    if (idx >= NLT) return;
    const int n = idx / LDIM, r = idx - n * LDIM;

    float* pm = out + NCONF;
    float* pj = pm + NLT;
    float* pk = pj + NLT;
    float* pc = pk + 2 * NLT;

    unsigned long long key = g_rkey[idx];
    unsigned bits = (unsigned)(key >> 32);
    int c = SDIM - 1 - (int)(unsigned)(key & 0xffffffffu);
    float cf = __uint_as_float(bits);

    int i0 = r / W0C, j0 = r - i0 * W0C;
    int i1 = c / W1C, j1 = c - i1 * W1C;
    bool m = (cf > THRV)
          && (i0 >= 2) && (i0 < H0C - 2) && (j0 >= 2) && (j0 < W0C - 2)
          && (i1 >= 2) && (i1 < H1C - 2) && (j1 >= 2) && (j1 < W1C - 2)
          && (bits == g_ccmax[n * SDIM + c]);

    if (m) {
        pm[idx] = 1.f;
        pj[idx] = (float)c;
        pk[2 * idx]     = (float)j1;
        pk[2 * idx + 1] = (float)i1;
        pc[idx] = cf;
    } else {
        pm[idx] = 0.f;
        pj[idx] = 0.f;
        pk[2 * idx] = 0.f;
        pk[2 * idx + 1] = 0.f;
        pc[idx] = 0.f;
    }
}

// ---------------- launch ----------------------------------------------------
extern "C" void kernel_launch(void* const* d_in, const int* in_sizes, int n_in,
                              void* d_out, int out_size) {
    const float* f0 = (const float*)d_in[0];
    const float* f1 = (const float*)d_in[1];
    float* out = (float*)d_out;

    static int s_attr_done = 0;
    if (!s_attr_done) {
        cudaFuncSetAttribute(k_gemm, cudaFuncAttributeMaxDynamicSharedMemorySize,
                             SMEM_TOTAL);
        cudaFuncSetAttribute(k_conf, cudaFuncAttributeMaxDynamicSharedMemorySize,
                             CONF_SMEM);
        s_attr_done = 1;
    }

    k_init<<<38, 256>>>();
    k_split<<<2400, 256>>>(f0, f1);
    {
        dim3 g(38, 38, NB);
        k_gemm<<<g, 256, SMEM_TOTAL>>>();
    }
    {
        dim3 g(19, 150, NB);
        k_conf<<<g, 256, CONF_SMEM>>>(out);
    }
    k_extract<<<38, 256>>>(out);
}

// round 15
// speedup vs baseline: 1.8318x; 1.1701x over previous
#include <cuda_runtime.h>
#include <cuda_bf16.h>
#include <cstdint>

// ---------------- problem constants ----------------------------------------
#define NB   2
#define LDIM 4800
#define SDIM 4800
#define CD   256
#define W0C  80
#define H0C  60
#define W1C  80
#define H1C  60
#define THRV 0.2f
#define SIM_SCALE 0.0390625f   // 1/(C*temp) = 1/(256*0.1)

#define NLT (NB*LDIM)
#define NST (NB*SDIM)
#define NCONF ((size_t)NB*(size_t)LDIM*(size_t)SDIM)

// GEMM tiling: 128x128 block tile, k-chunk 64 bf16, 8 warps (4 M x 2 N)
#define BUF_SZ 16384
#define STAGE_SZ (4*BUF_SZ)          // Ah, Al, Bh, Bl per stage
#define SMEM_TOTAL (2*STAGE_SZ)      // double buffered (128 KB)

// k_conf smem: 16x256 u64 keys (32 KB) + 16 rinv
#define CONF_SMEM (16*256*8 + 16*4)

// ---------------- device scratch -------------------------------------------
__device__ __align__(16) __nv_bfloat16 g_f0h[(size_t)NB*LDIM*CD];
__device__ __align__(16) __nv_bfloat16 g_f0l[(size_t)NB*LDIM*CD];
__device__ __align__(16) __nv_bfloat16 g_f1h[(size_t)NB*SDIM*CD];
__device__ __align__(16) __nv_bfloat16 g_f1l[(size_t)NB*SDIM*CD];
__device__ float g_e[(size_t)NB*LDIM*SDIM];     // exp(sim), 184 MB
__device__ float g_rsum[NLT];
__device__ float g_csum[NST];
__device__ unsigned long long g_rkey[NLT];      // (conf_bits<<32)|(SDIM-1-col)
__device__ unsigned g_ccmax[NST];

// ---------------- helpers ---------------------------------------------------
__device__ __forceinline__ unsigned smem_u32(const void* p) {
    unsigned a;
    asm("{ .reg .u64 t; cvta.to.shared.u64 t, %1; cvt.u32.u64 %0, t; }"
        : "=r"(a) : "l"(p));
    return a;
}
__device__ __forceinline__ unsigned swz(unsigned off) {
    return off ^ ((off >> 3) & 0x70);
}
#define LDSM4(r, a) \
    asm volatile("ldmatrix.sync.aligned.m8n8.x4.shared.b16 {%0,%1,%2,%3}, [%4];" \
        : "=r"((r)[0]), "=r"((r)[1]), "=r"((r)[2]), "=r"((r)[3]) : "r"(a))

#define CPA16(dst, src) \
    asm volatile("cp.async.cg.shared.global [%0], [%1], 16;" \
        :: "r"(dst), "l"(src) : "memory")
#define CPA_COMMIT() asm volatile("cp.async.commit_group;" ::: "memory")
#define CPA_WAIT1()  asm volatile("cp.async.wait_group 1;" ::: "memory")
#define CPA_WAIT0()  asm volatile("cp.async.wait_group 0;" ::: "memory")

__device__ __forceinline__ void mma16816(float* d, const unsigned* a,
                                         const unsigned* b) {
    asm volatile(
        "mma.sync.aligned.m16n8k16.row.col.f32.bf16.bf16.f32 "
        "{%0,%1,%2,%3}, {%4,%5,%6,%7}, {%8,%9}, {%0,%1,%2,%3};"
        : "+f"(d[0]), "+f"(d[1]), "+f"(d[2]), "+f"(d[3])
        : "r"(a[0]), "r"(a[1]), "r"(a[2]), "r"(a[3]), "r"(b[0]), "r"(b[1]));
}

// ---------------- kernel: init ---------------------------------------------
__global__ void k_init() {
    int i = blockIdx.x * 256 + threadIdx.x;
    if (i < NLT) { g_rsum[i] = 0.f; g_rkey[i] = 0ull; }
    if (i < NST) { g_csum[i] = 0.f; g_ccmax[i] = 0u; }
}

// ---------------- kernel: fp32 -> bf16 hi/lo split -------------------------
__device__ __forceinline__ unsigned pack_hi(float x, float y, float& lx, float& ly) {
    __nv_bfloat16 hx = __float2bfloat16_rn(x);
    __nv_bfloat16 hy = __float2bfloat16_rn(y);
    lx = x - __bfloat162float(hx);
    ly = y - __bfloat162float(hy);
    return ((unsigned)__bfloat16_as_ushort(hy) << 16) | (unsigned)__bfloat16_as_ushort(hx);
}
__device__ __forceinline__ unsigned pack_lo(float lx, float ly) {
    return ((unsigned)__bfloat16_as_ushort(__float2bfloat16_rn(ly)) << 16)
         | (unsigned)__bfloat16_as_ushort(__float2bfloat16_rn(lx));
}

__global__ void k_split(const float* __restrict__ f0, const float* __restrict__ f1) {
    int i = blockIdx.x * 256 + threadIdx.x;   // float4 group; 614400 total
    {
        float4 a = ((const float4*)f0)[i];
        a.x *= SIM_SCALE; a.y *= SIM_SCALE; a.z *= SIM_SCALE; a.w *= SIM_SCALE;
        float l0, l1, l2, l3;
        uint2 h, l;
        h.x = pack_hi(a.x, a.y, l0, l1);
        h.y = pack_hi(a.z, a.w, l2, l3);
        l.x = pack_lo(l0, l1);
        l.y = pack_lo(l2, l3);
        ((uint2*)g_f0h)[i] = h;
        ((uint2*)g_f0l)[i] = l;
    }
    {
        float4 a = ((const float4*)f1)[i];
        float l0, l1, l2, l3;
        uint2 h, l;
        h.x = pack_hi(a.x, a.y, l0, l1);
        h.y = pack_hi(a.z, a.w, l2, l3);
        l.x = pack_lo(l0, l1);
        l.y = pack_lo(l2, l3);
        ((uint2*)g_f1h)[i] = h;
        ((uint2*)g_f1l)[i] = l;
    }
}

// ---------------- kernel: HMMA split-bf16 GEMM + fused exp/sums ------------
// grid (38, 38, NB), 256 threads; cp.async double-buffered mainloop.
// (At the mma.sync FLOP roofline ~246us; do not touch.)
__global__ void __launch_bounds__(256, 1) k_gemm() {
    extern __shared__ char smem[];
    const unsigned sbase = smem_u32(smem);
    const int tid = threadIdx.x, wid = tid >> 5, lane = tid & 31;
    const int wm = wid & 3, wn = wid >> 2;
    const int lm = lane >> 2, lq = lane & 3;
    const int n = blockIdx.z;
    const int l0 = blockIdx.y * 128;
    const int s0 = blockIdx.x * 128;

    const int4* srcA[8];
    const int4* srcB[8];
    unsigned dstu[4];
    {
        const int4* pAh = (const int4*)g_f0h + (size_t)n * LDIM * 32;
        const int4* pAl = (const int4*)g_f0l + (size_t)n * LDIM * 32;
        const int4* pBh = (const int4*)g_f1h + (size_t)n * SDIM * 32;
        const int4* pBl = (const int4*)g_f1l + (size_t)n * SDIM * 32;
#pragma unroll
        for (int i = 0; i < 4; i++) {
            int idx = tid + i * 256;
            int r = idx >> 3, j = idx & 7;
            int ra = min(l0 + r, LDIM - 1);
            int rb = min(s0 + r, SDIM - 1);
            srcA[i]     = pAh + (size_t)ra * 32 + j;
            srcA[4 + i] = pAl + (size_t)ra * 32 + j;
            srcB[i]     = pBh + (size_t)rb * 32 + j;
            srcB[4 + i] = pBl + (size_t)rb * 32 + j;
            dstu[i] = sbase + swz(r * 128 + j * 16);
        }
    }

    unsigned aA[2], aB[4];
#pragma unroll
    for (int mf = 0; mf < 2; mf++) {
        unsigned row = wm * 32 + mf * 16 + (lane & 15);
        aA[mf] = sbase + (swz(row * 128) ^ ((lane >> 4) * 16));
    }
#pragma unroll
    for (int np = 0; np < 4; np++) {
        unsigned row = wn * 64 + np * 16 + ((lane >> 4) & 1) * 8 + (lane & 7);
        aB[np] = sbase + (swz(row * 128) ^ (((lane >> 3) & 1) * 16));
    }

    float acc[2][8][4];
#pragma unroll
    for (int mf = 0; mf < 2; mf++)
#pragma unroll
        for (int nf = 0; nf < 8; nf++)
#pragma unroll
            for (int q = 0; q < 4; q++) acc[mf][nf][q] = 0.f;

#pragma unroll
    for (int i = 0; i < 4; i++) {
        CPA16(dstu[i],                      srcA[i]);
        CPA16(dstu[i] + BUF_SZ,             srcA[4 + i]);
        CPA16(dstu[i] + 2 * BUF_SZ,         srcB[i]);
        CPA16(dstu[i] + 3 * BUF_SZ,         srcB[4 + i]);
    }
    CPA_COMMIT();

    for (int c = 0; c < 4; c++) {
        if (c < 3) {
            const unsigned so = ((c + 1) & 1) * STAGE_SZ;
#pragma unroll
            for (int i = 0; i < 4; i++) {
                CPA16(dstu[i] + so,              srcA[i] + (c + 1) * 8);
                CPA16(dstu[i] + so + BUF_SZ,     srcA[4 + i] + (c + 1) * 8);
                CPA16(dstu[i] + so + 2 * BUF_SZ, srcB[i] + (c + 1) * 8);
                CPA16(dstu[i] + so + 3 * BUF_SZ, srcB[4 + i] + (c + 1) * 8);
            }
            CPA_COMMIT();
            CPA_WAIT1();
        } else {
            CPA_WAIT0();
        }
        __syncthreads();

        const unsigned st = (c & 1) * STAGE_SZ;
#pragma unroll
        for (int ks = 0; ks < 4; ks++) {
            const unsigned kb = ks * 32;
            unsigned ah[2][4], al[2][4], bh[4][4], bl[4][4];
#pragma unroll
            for (int mf = 0; mf < 2; mf++) {
                LDSM4(ah[mf], ((aA[mf] ^ kb) + st));
                LDSM4(al[mf], ((aA[mf] ^ kb) + st) + BUF_SZ);
            }
#pragma unroll
            for (int np = 0; np < 4; np++) {
                LDSM4(bh[np], ((aB[np] ^ kb) + st) + 2 * BUF_SZ);
                LDSM4(bl[np], ((aB[np] ^ kb) + st) + 3 * BUF_SZ);
            }
#pragma unroll
            for (int mf = 0; mf < 2; mf++)
#pragma unroll
                for (int np = 0; np < 4; np++) {
                    mma16816(acc[mf][2 * np + 0], ah[mf], &bh[np][0]);
                    mma16816(acc[mf][2 * np + 1], ah[mf], &bh[np][2]);
                }
#pragma unroll
            for (int mf = 0; mf < 2; mf++)
#pragma unroll
                for (int np = 0; np < 4; np++) {
                    mma16816(acc[mf][2 * np + 0], al[mf], &bh[np][0]);
                    mma16816(acc[mf][2 * np + 1], al[mf], &bh[np][2]);
                }
#pragma unroll
            for (int mf = 0; mf < 2; mf++)
#pragma unroll
                for (int np = 0; np < 4; np++) {
                    mma16816(acc[mf][2 * np + 0], ah[mf], &bl[np][0]);
                    mma16816(acc[mf][2 * np + 1], ah[mf], &bl[np][2]);
                }
        }
        __syncthreads();
    }

    // ---- epilogue: e = exp(sim), store, fused row/col sums ----
    float* srow = (float*)smem;          // [128]
    float* scol = srow + 128;            // [128]
    if (tid < 128) { srow[tid] = 0.f; scol[tid] = 0.f; }
    __syncthreads();

    float rs[2][2] = {{0.f, 0.f}, {0.f, 0.f}};
    float cs[8][2];
#pragma unroll
    for (int nf = 0; nf < 8; nf++) { cs[nf][0] = 0.f; cs[nf][1] = 0.f; }

#pragma unroll
    for (int mf = 0; mf < 2; mf++) {
        const int row0 = l0 + wm * 32 + mf * 16 + lm;
        const int row1 = row0 + 8;
        const bool vr0 = row0 < LDIM, vr1 = row1 < LDIM;
        const size_t b0 = ((size_t)n * LDIM + row0) * SDIM;
        const size_t b1 = ((size_t)n * LDIM + row1) * SDIM;
#pragma unroll
        for (int nf = 0; nf < 8; nf++) {
            const int col = s0 + wn * 64 + nf * 8 + lq * 2;
            const bool vc = col < SDIM;
            float e0 = __expf(acc[mf][nf][0]);
            float e1 = __expf(acc[mf][nf][1]);
            float e2 = __expf(acc[mf][nf][2]);
            float e3 = __expf(acc[mf][nf][3]);
            if (vr0 & vc) __stcs((float2*)&g_e[b0 + col], make_float2(e0, e1));
            if (vr1 & vc) __stcs((float2*)&g_e[b1 + col], make_float2(e2, e3));
            if (vc) {
                rs[mf][0] += e0 + e1;
                rs[mf][1] += e2 + e3;
                float f0 = vr0 ? e0 : 0.f, f1 = vr0 ? e1 : 0.f;
                float f2 = vr1 ? e2 : 0.f, f3 = vr1 ? e3 : 0.f;
                cs[nf][0] += f0 + f2;
                cs[nf][1] += f1 + f3;
            }
        }
    }
#pragma unroll
    for (int mf = 0; mf < 2; mf++)
#pragma unroll
        for (int h = 0; h < 2; h++) {
            float v = rs[mf][h];
            v += __shfl_xor_sync(0xffffffffu, v, 1);
            v += __shfl_xor_sync(0xffffffffu, v, 2);
            if (lq == 0) atomicAdd(&srow[wm * 32 + mf * 16 + h * 8 + lm], v);
        }
#pragma unroll
    for (int nf = 0; nf < 8; nf++)
#pragma unroll
        for (int p = 0; p < 2; p++) {
            float v = cs[nf][p];
            v += __shfl_xor_sync(0xffffffffu, v, 4);
            v += __shfl_xor_sync(0xffffffffu, v, 8);
            v += __shfl_xor_sync(0xffffffffu, v, 16);
            if (lm == 0) atomicAdd(&scol[wn * 64 + nf * 8 + lq * 2 + p], v);
        }
    __syncthreads();
    if (tid < 128) {
        if (l0 + tid < LDIM) atomicAdd(&g_rsum[n * LDIM + l0 + tid], srow[tid]);
        if (s0 + tid < SDIM) atomicAdd(&g_csum[n * SDIM + s0 + tid], scol[tid]);
    }
}

// ---------------- kernel: conf, vectorized two-phase -----------------------
// grid (5, 300, NB), 256 threads: tile = 16 rows x 1024 cols (4/thread).
// Phase 1: float4 streaming; per-(row,thread) best key -> 32KB smem.
// Phase 2: warp w reduces rows 2w,2w+1: 8 strided LDS.64 + shfl-reduce.
__global__ void __launch_bounds__(256) k_conf(float* __restrict__ out) {
    extern __shared__ unsigned long long ksm[];   // [16][256]
    float* srinv = (float*)(ksm + 16 * 256);      // [16]
    const int n = blockIdx.z, r0 = blockIdx.y * 16, c0 = blockIdx.x * 1024;
    const int tid = threadIdx.x, w = tid >> 5, lane = tid & 31;
    const int cb = c0 + (tid << 2);
    const bool cv = cb < SDIM;

    if (tid < 16) srinv[tid] = 1.0f / g_rsum[n * LDIM + r0 + tid];
    __syncthreads();

    float ci0 = 0.f, ci1 = 0.f, ci2 = 0.f, ci3 = 0.f;
    if (cv) {
        float4 c4 = *(const float4*)&g_csum[n * SDIM + cb];
        ci0 = 1.0f / c4.x; ci1 = 1.0f / c4.y;
        ci2 = 1.0f / c4.z; ci3 = 1.0f / c4.w;
    }
    unsigned cm0 = 0u, cm1 = 0u, cm2 = 0u, cm3 = 0u;
    const size_t ebase = ((size_t)n * LDIM + r0) * SDIM + cb;

#pragma unroll 4
    for (int rr = 0; rr < 16; rr++) {
        unsigned long long key = 0ull;
        if (cv) {
            const size_t off = ebase + (size_t)rr * SDIM;
            float4 v = __ldcs((const float4*)&g_e[off]);
            const float ri = srinv[rr];
            float f0 = v.x * v.x * ri * ci0;
            float f1 = v.y * v.y * ri * ci1;
            float f2 = v.z * v.z * ri * ci2;
            float f3 = v.w * v.w * ri * ci3;
            __stcs((float4*)&out[off], make_float4(f0, f1, f2, f3));
            unsigned b0 = __float_as_uint(f0), b1 = __float_as_uint(f1);
            unsigned b2 = __float_as_uint(f2), b3 = __float_as_uint(f3);
            cm0 = max(cm0, b0); cm1 = max(cm1, b1);
            cm2 = max(cm2, b2); cm3 = max(cm3, b3);
            unsigned m = max(max(b0, b1), max(b2, b3));
            int j = (b0 == m) ? 0 : (b1 == m) ? 1 : (b2 == m) ? 2 : 3;
            key = ((unsigned long long)m << 32)
                | (unsigned)(SDIM - 1 - (cb + j));
        }
        ksm[rr * 256 + tid] = key;
    }
    if (cv) {
        atomicMax(&g_ccmax[n * SDIM + cb + 0], cm0);
        atomicMax(&g_ccmax[n * SDIM + cb + 1], cm1);
        atomicMax(&g_ccmax[n * SDIM + cb + 2], cm2);
        atomicMax(&g_ccmax[n * SDIM + cb + 3], cm3);
    }
    __syncthreads();

    // phase 2: warp w -> rows 2w, 2w+1
#pragma unroll
    for (int rr = 0; rr < 2; rr++) {
        const int row = w * 2 + rr;
        unsigned long long key = 0ull;
#pragma unroll
        for (int i = 0; i < 8; i++) {
            unsigned long long t = ksm[row * 256 + lane + 32 * i];
            key = (t > key) ? t : key;
        }
#pragma unroll
        for (int o = 16; o > 0; o >>= 1) {
            unsigned long long ok = __shfl_xor_sync(0xffffffffu, key, o);
            key = (ok > key) ? ok : key;
        }
        if (lane == 0) atomicMax(&g_rkey[n * LDIM + r0 + row], key);
    }
}

// ---------------- kernel: match extraction (O(L)) --------------------------
__global__ void k_extract(float* __restrict__ out) {
    int idx = blockIdx.x * 256 + threadIdx.x;
    if (idx >= NLT) return;
    const int n = idx / LDIM, r = idx - n * LDIM;

    float* pm = out + NCONF;
    float* pj = pm + NLT;
    float* pk = pj + NLT;
    float* pc = pk + 2 * NLT;

    unsigned long long key = g_rkey[idx];
    unsigned bits = (unsigned)(key >> 32);
    int c = SDIM - 1 - (int)(unsigned)(key & 0xffffffffu);
    float cf = __uint_as_float(bits);

    int i0 = r / W0C, j0 = r - i0 * W0C;
    int i1 = c / W1C, j1 = c - i1 * W1C;
    bool m = (cf > THRV)
          && (i0 >= 2) && (i0 < H0C - 2) && (j0 >= 2) && (j0 < W0C - 2)
          && (i1 >= 2) && (i1 < H1C - 2) && (j1 >= 2) && (j1 < W1C - 2)
          && (bits == g_ccmax[n * SDIM + c]);

    if (m) {
        pm[idx] = 1.f;
        pj[idx] = (float)c;
        pk[2 * idx]     = (float)j1;
        pk[2 * idx + 1] = (float)i1;
        pc[idx] = cf;
    } else {
        pm[idx] = 0.f;
        pj[idx] = 0.f;
        pk[2 * idx] = 0.f;
        pk[2 * idx + 1] = 0.f;
        pc[idx] = 0.f;
    }
}

// ---------------- launch ----------------------------------------------------
extern "C" void kernel_launch(void* const* d_in, const int* in_sizes, int n_in,
                              void* d_out, int out_size) {
    const float* f0 = (const float*)d_in[0];
    const float* f1 = (const float*)d_in[1];
    float* out = (float*)d_out;

    static int s_attr_done = 0;
    if (!s_attr_done) {
        cudaFuncSetAttribute(k_gemm, cudaFuncAttributeMaxDynamicSharedMemorySize,
                             SMEM_TOTAL);
        cudaFuncSetAttribute(k_conf, cudaFuncAttributeMaxDynamicSharedMemorySize,
                             CONF_SMEM);
        s_attr_done = 1;
    }

    k_init<<<38, 256>>>();
    k_split<<<2400, 256>>>(f0, f1);
    {
        dim3 g(38, 38, NB);
        k_gemm<<<g, 256, SMEM_TOTAL>>>();
    }
    {
        dim3 g(5, 300, NB);   // 1024-col x 16-row tiles
        k_conf<<<g, 256, CONF_SMEM>>>(out);
    }
    k_extract<<<38, 256>>>(out);
}